// round 4
// baseline (speedup 1.0000x reference)
#include <cuda_runtime.h>
#include <cuda_bf16.h>

#define EMBED_DIM 128
#define MAX_ATOM_TYPE 119
#define ROW 132                                    // padded row: 528B, 16B aligned
#define W_ELEMS (EMBED_DIM * MAX_ATOM_TYPE)        // 15232
#define TABLE_ELEMS (MAX_ATOM_TYPE * ROW)

// Fused table T[t][e] = W[e][t] + b[e], built once, shared by all SMs via L1/L2.
// 62.8KB -> resident in every SM's 228KB L1D (no smem used by gather kernel;
// streaming stores are no-allocate in L1 so the table is never evicted).
__device__ float g_table[TABLE_ELEMS];

__global__ void build_table_kernel(const float* __restrict__ W,
                                   const float* __restrict__ b)
{
    int i = blockIdx.x * blockDim.x + threadIdx.x;
    if (i < W_ELEMS) {
        int e = i / MAX_ATOM_TYPE;
        int t = i - e * MAX_ATOM_TYPE;
        g_table[t * ROW + e] = W[i] + __ldg(&b[e]);
    }
}

// Warp-per-32-atoms gather. No smem, low regs -> 6 CTAs/SM (48 warps), 2x the
// occupancy of the smem-table version. Per atom: shfl-distributed index,
// LDG.128 L1-hit from the resident table, streaming STG.128 to the output row.
__global__ void __launch_bounds__(256, 6)
embed_atom_kernel(const int* __restrict__ atom_type,
                  float4* __restrict__ out,        // [N, 32] float4 view
                  int n)
{
    const int warp = threadIdx.x >> 5;
    const int lane = threadIdx.x & 31;
    const int gwarp = blockIdx.x * (blockDim.x >> 5) + warp;
    const int nwarps = gridDim.x * (blockDim.x >> 5);

    const int nchunks = n >> 5;
    const float* lane_tab = g_table + (lane << 2);   // lane's 16B slot in a row

    for (int c = gwarp; c < nchunks; c += nwarps) {
        const int base = c << 5;
        int t_lane = __ldcs(&atom_type[base + lane]);    // coalesced 128B, evict-first

        float4* orow = out + (size_t)base * 32 + lane;

        #pragma unroll 8
        for (int k = 0; k < 32; k++) {
            int t = __shfl_sync(0xFFFFFFFFu, t_lane, k);
            float4 v = *reinterpret_cast<const float4*>(lane_tab + t * ROW);  // L1 hit
            __stcs(&orow[(size_t)k * 32], v);            // streaming STG.128
        }
    }

    // tail (n not multiple of 32)
    for (int a = (nchunks << 5) + gwarp; a < n; a += nwarps) {
        int t = __ldg(&atom_type[a]);
        float4 v = *reinterpret_cast<const float4*>(lane_tab + t * ROW);
        __stcs(&out[(size_t)a * 32 + lane], v);
    }
}

extern "C" void kernel_launch(void* const* d_in, const int* in_sizes, int n_in,
                              void* d_out, int out_size)
{
    const int*   atom_type = (const int*)d_in[0];
    const float* W         = (const float*)d_in[1];
    const float* b         = (const float*)d_in[2];
    float4*      out       = (float4*)d_out;
    int n = in_sizes[0];

    build_table_kernel<<<(W_ELEMS + 255) / 256, 256>>>(W, b);
    embed_atom_kernel<<<148 * 6, 256>>>(atom_type, out, n);
}

// round 5
// speedup vs baseline: 1.0338x; 1.0338x over previous
#include <cuda_runtime.h>
#include <cuda_bf16.h>

#define EMBED_DIM 128
#define MAX_ATOM_TYPE 119
#define ROW 132                                    // padded row: 528B, 16B aligned
#define W_ELEMS (EMBED_DIM * MAX_ATOM_TYPE)        // 15232
#define TABLE_ELEMS (MAX_ATOM_TYPE * ROW)

// Fused table T[t][e] = W[e][t] + b[e]; 62.8KB, L1-resident in every SM during
// the gather kernel (no smem used; streaming stores don't allocate in L1).
__device__ float g_table[TABLE_ELEMS];

__global__ void build_table_kernel(const float* __restrict__ W,
                                   const float* __restrict__ b)
{
    int i = blockIdx.x * blockDim.x + threadIdx.x;
    if (i < W_ELEMS) {
        int e = i / MAX_ATOM_TYPE;
        int t = i - e * MAX_ATOM_TYPE;
        g_table[t * ROW + e] = W[i] + __ldg(&b[e]);
    }
}

// Warp-per-32-atoms gather at full occupancy (8 CTAs/SM = 64 warps).
// Per atom: scalar broadcast LDG of the index (1 sector, L1-hit 31/32 times,
// no shfl dependency -> ptxas front-batches the known-address index loads),
// LDG.128 of the 16B lane slot from the L1-resident table, streaming STG.128.
__global__ void __launch_bounds__(256, 8)
embed_atom_kernel(const int* __restrict__ atom_type,
                  float4* __restrict__ out,        // [N, 32] float4 view
                  int n)
{
    const int warp = threadIdx.x >> 5;
    const int lane = threadIdx.x & 31;
    const int gwarp = blockIdx.x * (blockDim.x >> 5) + warp;
    const int nwarps = gridDim.x * (blockDim.x >> 5);

    const int nchunks = n >> 5;
    const float* lane_tab = g_table + (lane << 2);   // lane's 16B slot in a row

    for (int c = gwarp; c < nchunks; c += nwarps) {
        const int base = c << 5;
        const int* idx = atom_type + base;
        float4* orow = out + (size_t)base * 32 + lane;

        #pragma unroll 4
        for (int k = 0; k < 32; k++) {
            int t = __ldg(&idx[k]);                  // scalar broadcast, L1-hit
            float4 v = *reinterpret_cast<const float4*>(lane_tab + t * ROW);
            __stcs(&orow[(size_t)k * 32], v);        // streaming STG.128
        }
    }

    // tail (n not multiple of 32)
    for (int a = (nchunks << 5) + gwarp; a < n; a += nwarps) {
        int t = __ldg(&atom_type[a]);
        float4 v = *reinterpret_cast<const float4*>(lane_tab + t * ROW);
        __stcs(&out[(size_t)a * 32 + lane], v);
    }
}

extern "C" void kernel_launch(void* const* d_in, const int* in_sizes, int n_in,
                              void* d_out, int out_size)
{
    const int*   atom_type = (const int*)d_in[0];
    const float* W         = (const float*)d_in[1];
    const float* b         = (const float*)d_in[2];
    float4*      out       = (float4*)d_out;
    int n = in_sizes[0];

    build_table_kernel<<<(W_ELEMS + 255) / 256, 256>>>(W, b);
    embed_atom_kernel<<<148 * 8, 256>>>(atom_type, out, n);
}